// round 16
// baseline (speedup 1.0000x reference)
#include <cuda_runtime.h>
#include <cuda_fp16.h>
#include <math.h>
#include <stdint.h>

#define NBATCH 192
#define NTOK   256
#define CDIM   256
#define NH     8
#define HD     32
#define QKVD   768   // 3*C

#define LOG2E 1.4426950408889634f
#define SHIFT (-4.0f * 1.4426950408889634f)   // overflow-guard (half-domain safe)

// ---------------- scratch (static __device__, no runtime alloc) ----------------
__device__ __half g_qkv  [NBATCH * NTOK * QKVD];   // fp16, Q pre-scaled by scale*log2e
__device__ __half g_cmb  [64 * NH * NTOK * NTOK];  // (bias+mask)*log2e, fp16
__device__ __half g_biasb[NTOK * NTOK * NH];       // bias*log2e, [token-pair][head] fp16
__device__ __half g_att  [NBATCH * NTOK * CDIM];   // attention out fp16
__device__ __half g_xh   [NBATCH * NTOK * CDIM];   // x in fp16
__device__ __half g_wh   [QKVD * CDIM + CDIM * CDIM]; // fp16 qkv_w | proj_w

// ---------------- helpers ----------------
__device__ __forceinline__ void cp16(uint32_t saddr, const void* g) {
    asm volatile("cp.async.cg.shared.global [%0], [%1], 16;" :: "r"(saddr), "l"(g));
}
__device__ __forceinline__ void cp_commit() { asm volatile("cp.async.commit_group;"); }
__device__ __forceinline__ void mma_f16(float c[4], const uint32_t a[4], const uint32_t b[2]) {
    asm volatile(
        "mma.sync.aligned.m16n8k16.row.col.f32.f16.f16.f32 "
        "{%0,%1,%2,%3}, {%4,%5,%6,%7}, {%8,%9}, {%0,%1,%2,%3};"
        : "+f"(c[0]), "+f"(c[1]), "+f"(c[2]), "+f"(c[3])
        : "r"(a[0]), "r"(a[1]), "r"(a[2]), "r"(a[3]), "r"(b[0]), "r"(b[1]));
}
__device__ __forceinline__ void ldsm_x4(uint32_t r[4], uint32_t saddr) {
    asm volatile("ldmatrix.sync.aligned.m8n8.x4.shared.b16 {%0,%1,%2,%3}, [%4];"
        : "=r"(r[0]), "=r"(r[1]), "=r"(r[2]), "=r"(r[3]) : "r"(saddr));
}
__device__ __forceinline__ void ldsm_x4t(uint32_t r[4], uint32_t saddr) {
    asm volatile("ldmatrix.sync.aligned.m8n8.x4.trans.shared.b16 {%0,%1,%2,%3}, [%4];"
        : "=r"(r[0]), "=r"(r[1]), "=r"(r[2]), "=r"(r[3]) : "r"(saddr));
}
__device__ __forceinline__ void ldsm_x2t(uint32_t r[2], uint32_t saddr) {
    asm volatile("ldmatrix.sync.aligned.m8n8.x2.trans.shared.b16 {%0,%1}, [%2];"
        : "=r"(r[0]), "=r"(r[1]) : "r"(saddr));
}
__device__ __forceinline__ uint32_t packh2(float a, float b) {
    __half2 h = __floats2half2_rn(a, b);
    return *(uint32_t*)&h;
}
__device__ __forceinline__ uint32_t ex2h2(uint32_t x) {
    uint32_t r; asm("ex2.approx.f16x2 %0, %1;" : "=r"(r) : "r"(x)); return r;
}

// ---------------- prep: single fused fp32->fp16 over x | qkv_w | proj_w -------
#define NX2 (NBATCH * NTOK * CDIM / 2)
#define NW2 (QKVD * CDIM / 2)
#define NP2 (CDIM * CDIM / 2)
__global__ void tohalf3_kernel(const float2* __restrict__ x,
                               const float2* __restrict__ qw,
                               const float2* __restrict__ pw) {
    int i = blockIdx.x * blockDim.x + threadIdx.x;
    float2 v;
    __half2* dst;
    if (i < NX2) {
        v = x[i];  dst = (__half2*)g_xh + i;
    } else if (i < NX2 + NW2) {
        int j = i - NX2;
        v = qw[j]; dst = (__half2*)g_wh + j;
    } else if (i < NX2 + NW2 + NP2) {
        int j = i - NX2 - NW2;
        v = pw[j]; dst = (__half2*)g_wh + NW2 + j;
    } else return;
    *dst = __floats2half2_rn(v.x, v.y);
}

// ---------------- step 1: gather bias once -> [token][head] half --------------
__global__ void bias16_kernel(const float* __restrict__ table,
                              const int*   __restrict__ ridx) {
    int t = blockIdx.x * blockDim.x + threadIdx.x;
    if (t >= NTOK * NTOK) return;
    int r = ridx[t];
    __half hb[8];
    #pragma unroll
    for (int h = 0; h < NH; h++)
        hb[h] = __float2half_rn(table[r * NH + h] * LOG2E);
    *(uint4*)&g_biasb[t * NH] = *(uint4*)hb;
}

// ---------------- step 2: streaming combine: cmb = bias + mask*log2e ----------
__global__ void cmb_kernel(const float* __restrict__ mask) {
    int t = blockIdx.x * blockDim.x + threadIdx.x;
    int w = blockIdx.y;
    float2 mm = ((const float2*)mask)[((size_t)w << 15) + t];
    float mx = mm.x * LOG2E, my = mm.y * LOG2E;
    uint4 u0 = *(const uint4*)&g_biasb[(2 * t) * NH];
    uint4 u1 = *(const uint4*)&g_biasb[(2 * t + 1) * NH];
    const __half* b0 = (const __half*)&u0;
    const __half* b1 = (const __half*)&u1;
    __half2* c2 = (__half2*)g_cmb + ((size_t)(w * NH) << 15);
    #pragma unroll
    for (int h = 0; h < NH; h++) {
        float f0 = __half2float(b0[h]) + mx;
        float f1 = __half2float(b1[h]) + my;
        c2[((size_t)h << 15) + t] = __floats2half2_rn(f0, f1);
    }
}

// ---------------- fp16 NT GEMM, BK=64, 3-stage cp.async, 1 barrier/ktile ------
#define GRB 144
#define GSTB (128 * GRB)
template<bool QKV_MODE>
__global__ __launch_bounds__(256, 2)
void gemm_f16(const __half* __restrict__ A, const __half* __restrict__ B,
              const float* __restrict__ bias, void* __restrict__ Cv,
              int M, int N, int K)
{
    extern __shared__ __half smh[];
    const uint32_t smem0 = (uint32_t)__cvta_generic_to_shared(smh);
    const uint32_t AsB = smem0;
    const uint32_t BsB = smem0 + 3 * GSTB;

    const int tid  = threadIdx.x;
    const int warp = tid >> 5, lane = tid & 31;
    const int qg   = lane >> 2, tg = lane & 3;
    const int wm   = (warp >> 2) * 64;
    const int wn   = (warp & 3) * 32;
    const int row0 = blockIdx.y * 128, col0 = blockIdx.x * 128;

    const uint32_t aoff = (uint32_t)((lane & 15) * GRB + (lane >> 4) * 16) + (uint32_t)(wm * GRB);
    const uint32_t boff = (uint32_t)(((lane & 7) + 8 * ((lane >> 4) & 1)) * GRB
                                     + ((lane >> 3) & 1) * 16) + (uint32_t)(wn * GRB);

    float c[4][4][4];
    #pragma unroll
    for (int i = 0; i < 4; i++)
        #pragma unroll
        for (int j = 0; j < 4; j++)
            #pragma unroll
            for (int t = 0; t < 4; t++) c[i][j][t] = 0.0f;

    const int KT = K / 64;

    auto load_stage = [&](int stage, int k0) {
        #pragma unroll
        for (int i = 0; i < 4; i++) {
            int id = tid + i * 256;
            int r = id >> 3, c8 = (id & 7) * 8;
            cp16(AsB + stage * GSTB + r * GRB + (id & 7) * 16,
                 A + (size_t)(row0 + r) * K + k0 + c8);
            cp16(BsB + stage * GSTB + r * GRB + (id & 7) * 16,
                 B + (size_t)(col0 + r) * K + k0 + c8);
        }
        cp_commit();
    };

    load_stage(0, 0);
    load_stage(1, 64);

    for (int kt = 0; kt < KT; kt++) {
        if (kt < KT - 1) { asm volatile("cp.async.wait_group 1;"); }
        else             { asm volatile("cp.async.wait_group 0;"); }
        __syncthreads();
        if (kt + 2 < KT) load_stage((kt + 2) % 3, (kt + 2) * 64);

        const uint32_t Asb = AsB + (kt % 3) * GSTB;
        const uint32_t Bsb = BsB + (kt % 3) * GSTB;

        #pragma unroll
        for (int ks = 0; ks < 4; ks++) {
            uint32_t af[4][4], bf[4][2];
            #pragma unroll
            for (int i = 0; i < 4; i++)
                ldsm_x4(af[i], Asb + aoff + i * 16 * GRB + ks * 32);
            #pragma unroll
            for (int jp = 0; jp < 2; jp++) {
                uint32_t bt[4];
                ldsm_x4(bt, Bsb + boff + jp * 16 * GRB + ks * 32);
                bf[2 * jp][0] = bt[0]; bf[2 * jp][1] = bt[1];
                bf[2 * jp + 1][0] = bt[2]; bf[2 * jp + 1][1] = bt[3];
            }
            #pragma unroll
            for (int i = 0; i < 4; i++)
                #pragma unroll
                for (int j = 0; j < 4; j++)
                    mma_f16(c[i][j], af[i], bf[j]);
        }
    }

    const float qscale = (float)(0.17677669529663687 * 1.4426950408889634);
    #pragma unroll
    for (int i = 0; i < 4; i++) {
        int row = row0 + wm + i * 16 + qg;
        #pragma unroll
        for (int j = 0; j < 4; j++) {
            int col = col0 + wn + j * 8 + 2 * tg;
            float b0 = bias[col], b1 = bias[col + 1];
            float v00 = c[i][j][0] + b0, v01 = c[i][j][1] + b1;
            float v10 = c[i][j][2] + b0, v11 = c[i][j][3] + b1;
            if (QKV_MODE) {
                if (col < 256) { v00 *= qscale; v01 *= qscale; v10 *= qscale; v11 *= qscale; }
                __half* C = (__half*)Cv;
                *(__half2*)&C[(size_t)row * N + col]       = __floats2half2_rn(v00, v01);
                *(__half2*)&C[(size_t)(row + 8) * N + col] = __floats2half2_rn(v10, v11);
            } else {
                float* C = (float*)Cv;
                *(float2*)&C[(size_t)row * N + col]       = make_float2(v00, v01);
                *(float2*)&C[(size_t)(row + 8) * N + col] = make_float2(v10, v11);
            }
        }
    }
}

// ---------------- fp16 flash attention: cp.async-staged cmb -------------------
#define ARB 80                      // row bytes for Q/K/V tiles
#define CMB_OFF (3 * 256 * ARB)     // 61440: cmb stages start here
#define CRB 80                      // cmb stage row bytes (32 cols=64B + pad; 16B-aligned, CF)
#define CSTG (256 * CRB)            // 20480 per stage
__global__ __launch_bounds__(256, 2)
void attn_f16()
{
    extern __shared__ __half smh[];
    char* smc = (char*)smh;
    const uint32_t smem0 = (uint32_t)__cvta_generic_to_shared(smh);
    const uint32_t QsB = smem0;
    const uint32_t KsB = smem0 + 256 * ARB;
    const uint32_t VsB = smem0 + 2 * 256 * ARB;
    const uint32_t CsB = smem0 + CMB_OFF;

    // rep-fastest decode: 3 consecutive CTAs share the same (window, head) cmb slice
    const int idx = blockIdx.x;          // 0..1535
    const int rep = idx % 3;
    const int wh  = idx / 3;
    const int h   = wh & 7;
    const int w   = wh >> 3;
    const int b   = rep * 64 + w;

    const int tid = threadIdx.x, warp = tid >> 5, lane = tid & 31;
    const int qg = lane >> 2, tg = lane & 3;

    const __half* base = g_qkv + (size_t)b * NTOK * QKVD + h * 32;
    const char*  cmbsrc = (const char*)(g_cmb + ((size_t)((w * NH + h)) << 16));

    // stage cmb slice for a 32-key block: row tid, 64 bytes (coalesced)
    auto stage_cmb = [&](int buf, int n0) {
        const char* src = cmbsrc + tid * 512 + n0 * 2;
        uint32_t dst = CsB + buf * CSTG + tid * CRB;
        cp16(dst,      src);
        cp16(dst + 16, src + 16);
        cp16(dst + 32, src + 32);
        cp16(dst + 48, src + 48);
    };

    // prologue: Q/K/V + cmb slice 0, one group
    #pragma unroll
    for (int i = 0; i < 4; i++) {
        int id = tid + i * 256;
        int m = id >> 2, cb = (id & 3) * 16;
        const __half* src = base + m * QKVD + (id & 3) * 8;
        cp16(QsB + m * ARB + cb, src);
        cp16(KsB + m * ARB + cb, src + 256);
        cp16(VsB + m * ARB + cb, src + 512);
    }
    stage_cmb(0, 0);
    cp_commit();

    // V ones-column: col 32 = 1.0, cols 33..39 = 0
    *(uint4*)(smc + 2 * 256 * ARB + tid * ARB + 64) = make_uint4(0x3C00u, 0u, 0u, 0u);

    asm volatile("cp.async.wait_group 0;");
    __syncthreads();

    const int wm = warp * 32;

    const uint32_t aoff = (uint32_t)((lane & 15) * ARB + (lane >> 4) * 16);
    const uint32_t koff = (uint32_t)(((lane & 7) + 8 * ((lane >> 4) & 1)) * ARB
                                     + ((lane >> 3) & 1) * 16);
    const uint32_t voff = aoff;
    const uint32_t v1off = (uint32_t)((lane & 15) * ARB + 64);

    uint32_t qf[2][2][4];
    #pragma unroll
    for (int i = 0; i < 2; i++)
        #pragma unroll
        for (int ks = 0; ks < 2; ks++)
            ldsm_x4(qf[i][ks], QsB + aoff + (wm + 16 * i) * ARB + ks * 32);

    float O[2][5][4];
    #pragma unroll
    for (int i = 0; i < 2; i++)
        #pragma unroll
        for (int j = 0; j < 5; j++)
            #pragma unroll
            for (int t = 0; t < 4; t++) O[i][j][t] = 0.0f;

    #pragma unroll 1
    for (int nb = 0; nb < 8; nb++) {
        const int n0 = nb * 32;
        const int buf = nb & 1;

        // prefetch next cmb slice; wait for current
        if (nb < 7) {
            stage_cmb(buf ^ 1, n0 + 32);
            cp_commit();
            asm volatile("cp.async.wait_group 1;");
        } else {
            asm volatile("cp.async.wait_group 0;");
        }
        __syncthreads();

        // ---- K fragments
        uint32_t kf[2][4][2];
        #pragma unroll
        for (int ks = 0; ks < 2; ks++)
            #pragma unroll
            for (int jp = 0; jp < 2; jp++) {
                uint32_t t4[4];
                ldsm_x4(t4, KsB + koff + (n0 + 16 * jp) * ARB + ks * 32);
                kf[ks][2 * jp][0] = t4[0]; kf[ks][2 * jp][1] = t4[1];
                kf[ks][2 * jp + 1][0] = t4[2]; kf[ks][2 * jp + 1][1] = t4[3];
            }

        // ---- S = Q K^T
        float S[2][4][4];
        #pragma unroll
        for (int i = 0; i < 2; i++)
            #pragma unroll
            for (int j = 0; j < 4; j++)
                #pragma unroll
                for (int t = 0; t < 4; t++) S[i][j][t] = 0.0f;
        #pragma unroll
        for (int ks = 0; ks < 2; ks++)
            #pragma unroll
            for (int j = 0; j < 4; j++) {
                mma_f16(S[0][j], qf[0][ks], kf[ks][j]);
                mma_f16(S[1][j], qf[1][ks], kf[ks][j]);
            }

        // ---- fold in cmb (bank-conflict-free LDS) + shift
        const char* cmB = smc + CMB_OFF + buf * CSTG;
        #pragma unroll
        for (int i = 0; i < 2; i++) {
            const char* p0 = cmB + (wm + 16 * i + qg) * CRB + tg * 4;
            const char* p1 = p0 + 8 * CRB;
            #pragma unroll
            for (int j = 0; j < 4; j++) {
                float2 v0 = __half22float2(*(const __half2*)(p0 + 16 * j));
                float2 v1 = __half22float2(*(const __half2*)(p1 + 16 * j));
                S[i][j][0] += v0.x + SHIFT;
                S[i][j][1] += v0.y + SHIFT;
                S[i][j][2] += v1.x + SHIFT;
                S[i][j][3] += v1.y + SHIFT;
            }
        }

        // ---- softmax: p = 2^S via f16x2 MUFU, straight into A-fragments
        uint32_t ph[2][2][4];
        #pragma unroll
        for (int i = 0; i < 2; i++)
            #pragma unroll
            for (int ks2 = 0; ks2 < 2; ks2++) {
                ph[i][ks2][0] = ex2h2(packh2(S[i][2 * ks2][0],     S[i][2 * ks2][1]));
                ph[i][ks2][1] = ex2h2(packh2(S[i][2 * ks2][2],     S[i][2 * ks2][3]));
                ph[i][ks2][2] = ex2h2(packh2(S[i][2 * ks2 + 1][0], S[i][2 * ks2 + 1][1]));
                ph[i][ks2][3] = ex2h2(packh2(S[i][2 * ks2 + 1][2], S[i][2 * ks2 + 1][3]));
            }

        // ---- V fragments + ones-column tile
        uint32_t vf[2][4][2], vf1[2][2];
        #pragma unroll
        for (int ks2 = 0; ks2 < 2; ks2++) {
            #pragma unroll
            for (int jp = 0; jp < 2; jp++) {
                uint32_t t4[4];
                ldsm_x4t(t4, VsB + voff + (n0 + 16 * ks2) * ARB + jp * 32);
                vf[ks2][2 * jp][0] = t4[0]; vf[ks2][2 * jp][1] = t4[1];
                vf[ks2][2 * jp + 1][0] = t4[2]; vf[ks2][2 * jp + 1][1] = t4[3];
            }
            ldsm_x2t(vf1[ks2], VsB + v1off + (n0 + 16 * ks2) * ARB);
        }

        // ---- O += P V (plus row-sum column)
        #pragma unroll
        for (int ks2 = 0; ks2 < 2; ks2++) {
            #pragma unroll
            for (int j = 0; j < 4; j++) {
                mma_f16(O[0][j], ph[0][ks2], vf[ks2][j]);
                mma_f16(O[1][j], ph[1][ks2], vf[ks2][j]);
            }
            mma_f16(O[0][4], ph[0][ks2], vf1[ks2]);
            mma_f16(O[1][4], ph[1][ks2], vf1[ks2]);
        }

        __syncthreads();   // all reads of buf done before next iter's cp writes it
    }

    #pragma unroll
    for (int i = 0; i < 2; i++) {
        float s0 = __shfl_sync(0xffffffffu, O[i][4][0], lane & 28);
        float s1 = __shfl_sync(0xffffffffu, O[i][4][2], lane & 28);
        float inv0 = 1.0f / s0, inv1 = 1.0f / s1;
        int row = wm + 16 * i + qg;
        #pragma unroll
        for (int j = 0; j < 4; j++) {
            int col = h * 32 + 8 * j + 2 * tg;
            *(__half2*)&g_att[((size_t)b * NTOK + row) * CDIM + col] =
                __floats2half2_rn(O[i][j][0] * inv0, O[i][j][1] * inv0);
            *(__half2*)&g_att[((size_t)b * NTOK + row + 8) * CDIM + col] =
                __floats2half2_rn(O[i][j][2] * inv1, O[i][j][3] * inv1);
        }
    }
}

// --------------------------------------------------------------------------
extern "C" void kernel_launch(void* const* d_in, const int* in_sizes, int n_in,
                              void* d_out, int out_size)
{
    const float* x      = (const float*)d_in[0];
    const float* mask   = (const float*)d_in[1];
    const float* qkv_w  = (const float*)d_in[2];
    const float* qkv_b  = (const float*)d_in[3];
    const float* proj_w = (const float*)d_in[4];
    const float* proj_b = (const float*)d_in[5];
    const float* table  = (const float*)d_in[6];
    const int*   ridx   = (const int*)d_in[7];
    float* out = (float*)d_out;

    __half *qkv_ptr, *att_ptr, *xh_ptr, *wh_ptr;
    cudaGetSymbolAddress((void**)&qkv_ptr, g_qkv);
    cudaGetSymbolAddress((void**)&att_ptr, g_att);
    cudaGetSymbolAddress((void**)&xh_ptr,  g_xh);
    cudaGetSymbolAddress((void**)&wh_ptr,  g_wh);
    __half* qkvw_h  = wh_ptr;
    __half* projw_h = wh_ptr + QKVD * CDIM;

    const int gemm_smem = 6 * GSTB;                  // 110592 B
    const int attn_smem = CMB_OFF + 2 * CSTG;        // 61440 + 40960 = 102400 B
    cudaFuncSetAttribute((const void*)gemm_f16<true>,
                         cudaFuncAttributeMaxDynamicSharedMemorySize, gemm_smem);
    cudaFuncSetAttribute((const void*)gemm_f16<false>,
                         cudaFuncAttributeMaxDynamicSharedMemorySize, gemm_smem);
    cudaFuncSetAttribute((const void*)attn_f16,
                         cudaFuncAttributeMaxDynamicSharedMemorySize, attn_smem);

    // 0) prep: one fused conversion + bias gather + cmb combine
    tohalf3_kernel<<<(NX2 + NW2 + NP2 + 255) / 256, 256>>>(
        (const float2*)x, (const float2*)qkv_w, (const float2*)proj_w);
    bias16_kernel<<<NTOK * NTOK / 256, 256>>>(table, ridx);
    cmb_kernel<<<dim3(128, 64), 256>>>(mask);

    // 2) QKV projection -> fp16 (Q pre-scaled by scale*log2e)
    gemm_f16<true><<<dim3(QKVD / 128, (NBATCH * NTOK) / 128), 256, gemm_smem>>>(
        xh_ptr, qkvw_h, qkv_b, qkv_ptr, NBATCH * NTOK, QKVD, CDIM);

    // 3) window attention
    attn_f16<<<NBATCH * NH, 256, attn_smem>>>();

    // 4) output projection -> fp32 d_out
    gemm_f16<false><<<dim3(CDIM / 128, (NBATCH * NTOK) / 128), 256, gemm_smem>>>(
        att_ptr, projw_h, proj_b, out, NBATCH * NTOK, CDIM, CDIM);
}

// round 17
// speedup vs baseline: 1.1457x; 1.1457x over previous
#include <cuda_runtime.h>
#include <cuda_fp16.h>
#include <math.h>
#include <stdint.h>

#define NBATCH 192
#define NTOK   256
#define CDIM   256
#define NH     8
#define HD     32
#define QKVD   768   // 3*C

#define LOG2E 1.4426950408889634f
#define SHIFT (-4.0f * 1.4426950408889634f)   // overflow-guard (half-domain safe)

// ---------------- scratch (static __device__, no runtime alloc) ----------------
__device__ __half g_qkv  [NBATCH * NTOK * QKVD];   // fp16, Q pre-scaled by scale*log2e
__device__ __half g_cmb  [64 * NH * NTOK * NTOK];  // (bias+mask)*log2e, fp16
__device__ __half g_biasb[NTOK * NTOK * NH];       // bias*log2e, [token-pair][head] fp16
__device__ __half g_att  [NBATCH * NTOK * CDIM];   // attention out fp16
__device__ __half g_xh   [NBATCH * NTOK * CDIM];   // x in fp16
__device__ __half g_wh   [QKVD * CDIM + CDIM * CDIM]; // fp16 qkv_w | proj_w

// ---------------- helpers ----------------
__device__ __forceinline__ void cp16(uint32_t saddr, const void* g) {
    asm volatile("cp.async.cg.shared.global [%0], [%1], 16;" :: "r"(saddr), "l"(g));
}
__device__ __forceinline__ void cp_commit() { asm volatile("cp.async.commit_group;"); }
__device__ __forceinline__ void mma_f16(float c[4], const uint32_t a[4], const uint32_t b[2]) {
    asm volatile(
        "mma.sync.aligned.m16n8k16.row.col.f32.f16.f16.f32 "
        "{%0,%1,%2,%3}, {%4,%5,%6,%7}, {%8,%9}, {%0,%1,%2,%3};"
        : "+f"(c[0]), "+f"(c[1]), "+f"(c[2]), "+f"(c[3])
        : "r"(a[0]), "r"(a[1]), "r"(a[2]), "r"(a[3]), "r"(b[0]), "r"(b[1]));
}
__device__ __forceinline__ void ldsm_x4(uint32_t r[4], uint32_t saddr) {
    asm volatile("ldmatrix.sync.aligned.m8n8.x4.shared.b16 {%0,%1,%2,%3}, [%4];"
        : "=r"(r[0]), "=r"(r[1]), "=r"(r[2]), "=r"(r[3]) : "r"(saddr));
}
__device__ __forceinline__ void ldsm_x4t(uint32_t r[4], uint32_t saddr) {
    asm volatile("ldmatrix.sync.aligned.m8n8.x4.trans.shared.b16 {%0,%1,%2,%3}, [%4];"
        : "=r"(r[0]), "=r"(r[1]), "=r"(r[2]), "=r"(r[3]) : "r"(saddr));
}
__device__ __forceinline__ void ldsm_x2t(uint32_t r[2], uint32_t saddr) {
    asm volatile("ldmatrix.sync.aligned.m8n8.x2.trans.shared.b16 {%0,%1}, [%2];"
        : "=r"(r[0]), "=r"(r[1]) : "r"(saddr));
}
__device__ __forceinline__ uint32_t packh2(float a, float b) {
    __half2 h = __floats2half2_rn(a, b);
    return *(uint32_t*)&h;
}
__device__ __forceinline__ uint32_t ex2h2(uint32_t x) {
    uint32_t r; asm("ex2.approx.f16x2 %0, %1;" : "=r"(r) : "r"(x)); return r;
}

// ---------------- prep: single fused fp32->fp16 over x | qkv_w | proj_w -------
#define NX2 (NBATCH * NTOK * CDIM / 2)
#define NW2 (QKVD * CDIM / 2)
#define NP2 (CDIM * CDIM / 2)
__global__ void tohalf3_kernel(const float2* __restrict__ x,
                               const float2* __restrict__ qw,
                               const float2* __restrict__ pw) {
    int i = blockIdx.x * blockDim.x + threadIdx.x;
    float2 v;
    __half2* dst;
    if (i < NX2) {
        v = x[i];  dst = (__half2*)g_xh + i;
    } else if (i < NX2 + NW2) {
        int j = i - NX2;
        v = qw[j]; dst = (__half2*)g_wh + j;
    } else if (i < NX2 + NW2 + NP2) {
        int j = i - NX2 - NW2;
        v = pw[j]; dst = (__half2*)g_wh + NW2 + j;
    } else return;
    *dst = __floats2half2_rn(v.x, v.y);
}

// ---------------- step 1: gather bias once -> [token][head] half --------------
__global__ void bias16_kernel(const float* __restrict__ table,
                              const int*   __restrict__ ridx) {
    int t = blockIdx.x * blockDim.x + threadIdx.x;
    if (t >= NTOK * NTOK) return;
    int r = ridx[t];
    __half hb[8];
    #pragma unroll
    for (int h = 0; h < NH; h++)
        hb[h] = __float2half_rn(table[r * NH + h] * LOG2E);
    *(uint4*)&g_biasb[t * NH] = *(uint4*)hb;
}

// ---------------- step 2: streaming combine: cmb = bias + mask*log2e ----------
__global__ void cmb_kernel(const float* __restrict__ mask) {
    int t = blockIdx.x * blockDim.x + threadIdx.x;
    int w = blockIdx.y;
    float2 mm = ((const float2*)mask)[((size_t)w << 15) + t];
    float mx = mm.x * LOG2E, my = mm.y * LOG2E;
    uint4 u0 = *(const uint4*)&g_biasb[(2 * t) * NH];
    uint4 u1 = *(const uint4*)&g_biasb[(2 * t + 1) * NH];
    const __half* b0 = (const __half*)&u0;
    const __half* b1 = (const __half*)&u1;
    __half2* c2 = (__half2*)g_cmb + ((size_t)(w * NH) << 15);
    #pragma unroll
    for (int h = 0; h < NH; h++) {
        float f0 = __half2float(b0[h]) + mx;
        float f1 = __half2float(b1[h]) + my;
        c2[((size_t)h << 15) + t] = __floats2half2_rn(f0, f1);
    }
}

// ---------------- fp16 NT GEMM, BK=64, 3-stage cp.async, 1 barrier/ktile ------
#define GRB 144
#define GSTB (128 * GRB)
template<bool QKV_MODE>
__global__ __launch_bounds__(256, 2)
void gemm_f16(const __half* __restrict__ A, const __half* __restrict__ B,
              const float* __restrict__ bias, void* __restrict__ Cv,
              int M, int N, int K)
{
    extern __shared__ __half smh[];
    const uint32_t smem0 = (uint32_t)__cvta_generic_to_shared(smh);
    const uint32_t AsB = smem0;
    const uint32_t BsB = smem0 + 3 * GSTB;

    const int tid  = threadIdx.x;
    const int warp = tid >> 5, lane = tid & 31;
    const int qg   = lane >> 2, tg = lane & 3;
    const int wm   = (warp >> 2) * 64;
    const int wn   = (warp & 3) * 32;
    const int row0 = blockIdx.y * 128, col0 = blockIdx.x * 128;

    const uint32_t aoff = (uint32_t)((lane & 15) * GRB + (lane >> 4) * 16) + (uint32_t)(wm * GRB);
    const uint32_t boff = (uint32_t)(((lane & 7) + 8 * ((lane >> 4) & 1)) * GRB
                                     + ((lane >> 3) & 1) * 16) + (uint32_t)(wn * GRB);

    float c[4][4][4];
    #pragma unroll
    for (int i = 0; i < 4; i++)
        #pragma unroll
        for (int j = 0; j < 4; j++)
            #pragma unroll
            for (int t = 0; t < 4; t++) c[i][j][t] = 0.0f;

    const int KT = K / 64;

    auto load_stage = [&](int stage, int k0) {
        #pragma unroll
        for (int i = 0; i < 4; i++) {
            int id = tid + i * 256;
            int r = id >> 3, c8 = (id & 7) * 8;
            cp16(AsB + stage * GSTB + r * GRB + (id & 7) * 16,
                 A + (size_t)(row0 + r) * K + k0 + c8);
            cp16(BsB + stage * GSTB + r * GRB + (id & 7) * 16,
                 B + (size_t)(col0 + r) * K + k0 + c8);
        }
        cp_commit();
    };

    load_stage(0, 0);
    load_stage(1, 64);

    for (int kt = 0; kt < KT; kt++) {
        if (kt < KT - 1) { asm volatile("cp.async.wait_group 1;"); }
        else             { asm volatile("cp.async.wait_group 0;"); }
        __syncthreads();
        if (kt + 2 < KT) load_stage((kt + 2) % 3, (kt + 2) * 64);

        const uint32_t Asb = AsB + (kt % 3) * GSTB;
        const uint32_t Bsb = BsB + (kt % 3) * GSTB;

        #pragma unroll
        for (int ks = 0; ks < 4; ks++) {
            uint32_t af[4][4], bf[4][2];
            #pragma unroll
            for (int i = 0; i < 4; i++)
                ldsm_x4(af[i], Asb + aoff + i * 16 * GRB + ks * 32);
            #pragma unroll
            for (int jp = 0; jp < 2; jp++) {
                uint32_t bt[4];
                ldsm_x4(bt, Bsb + boff + jp * 16 * GRB + ks * 32);
                bf[2 * jp][0] = bt[0]; bf[2 * jp][1] = bt[1];
                bf[2 * jp + 1][0] = bt[2]; bf[2 * jp + 1][1] = bt[3];
            }
            #pragma unroll
            for (int i = 0; i < 4; i++)
                #pragma unroll
                for (int j = 0; j < 4; j++)
                    mma_f16(c[i][j], af[i], bf[j]);
        }
    }

    const float qscale = (float)(0.17677669529663687 * 1.4426950408889634);
    #pragma unroll
    for (int i = 0; i < 4; i++) {
        int row = row0 + wm + i * 16 + qg;
        #pragma unroll
        for (int j = 0; j < 4; j++) {
            int col = col0 + wn + j * 8 + 2 * tg;
            float b0 = bias[col], b1 = bias[col + 1];
            float v00 = c[i][j][0] + b0, v01 = c[i][j][1] + b1;
            float v10 = c[i][j][2] + b0, v11 = c[i][j][3] + b1;
            if (QKV_MODE) {
                if (col < 256) { v00 *= qscale; v01 *= qscale; v10 *= qscale; v11 *= qscale; }
                __half* C = (__half*)Cv;
                *(__half2*)&C[(size_t)row * N + col]       = __floats2half2_rn(v00, v01);
                *(__half2*)&C[(size_t)(row + 8) * N + col] = __floats2half2_rn(v10, v11);
            } else {
                float* C = (float*)Cv;
                *(float2*)&C[(size_t)row * N + col]       = make_float2(v00, v01);
                *(float2*)&C[(size_t)(row + 8) * N + col] = make_float2(v10, v11);
            }
        }
    }
}

// ---------------- fp16 flash attention: warp-private cp.async cmb staging -----
#define ARB 80                       // row bytes for Q/K/V tiles
#define CMB_OFF (3 * 256 * ARB)      // 61440
#define CRB2 80                      // per-warp cmb row bytes (64B data + pad; CF)
#define CWST (32 * CRB2)             // 2560 per warp-stage
__global__ __launch_bounds__(256, 2)
void attn_f16()
{
    extern __shared__ __half smh[];
    char* smc = (char*)smh;
    const uint32_t smem0 = (uint32_t)__cvta_generic_to_shared(smh);
    const uint32_t QsB = smem0;
    const uint32_t KsB = smem0 + 256 * ARB;
    const uint32_t VsB = smem0 + 2 * 256 * ARB;

    // rep-fastest decode: 3 consecutive CTAs share the same (window, head) cmb slice
    const int idx = blockIdx.x;          // 0..1535
    const int rep = idx % 3;
    const int wh  = idx / 3;
    const int h   = wh & 7;
    const int w   = wh >> 3;
    const int b   = rep * 64 + w;

    const int tid = threadIdx.x, warp = tid >> 5, lane = tid & 31;
    const int qg = lane >> 2, tg = lane & 3;
    const int wm = warp * 32;

    const __half* base = g_qkv + (size_t)b * NTOK * QKVD + h * 32;
    const char* cmbsrc = (const char*)(g_cmb + ((size_t)((w * NH + h)) << 16));
    const uint32_t CsW = smem0 + CMB_OFF + (uint32_t)(warp * 2 * CWST);

    // stage the warp's 32 cmb rows x 64B for one 32-key block (per-warp, coalesced)
    auto stage_cmb = [&](int buf, int n0) {
        #pragma unroll
        for (int t = 0; t < 4; t++) {
            int task = lane + 32 * t;          // 0..127
            int row = task >> 2, ch = task & 3;
            cp16(CsW + buf * CWST + row * CRB2 + ch * 16,
                 cmbsrc + (size_t)(wm + row) * 512 + n0 * 2 + ch * 16);
        }
        cp_commit();
    };

    // prologue: Q/K/V + cmb slice 0
    #pragma unroll
    for (int i = 0; i < 4; i++) {
        int id = tid + i * 256;
        int m = id >> 2, cb = (id & 3) * 16;
        const __half* src = base + m * QKVD + (id & 3) * 8;
        cp16(QsB + m * ARB + cb, src);
        cp16(KsB + m * ARB + cb, src + 256);
        cp16(VsB + m * ARB + cb, src + 512);
    }
    cp_commit();
    stage_cmb(0, 0);

    // V ones-column: col 32 = 1.0, cols 33..39 = 0
    *(uint4*)(smc + 2 * 256 * ARB + tid * ARB + 64) = make_uint4(0x3C00u, 0u, 0u, 0u);

    asm volatile("cp.async.wait_group 0;");
    __syncthreads();

    const uint32_t aoff = (uint32_t)((lane & 15) * ARB + (lane >> 4) * 16);
    const uint32_t koff = (uint32_t)(((lane & 7) + 8 * ((lane >> 4) & 1)) * ARB
                                     + ((lane >> 3) & 1) * 16);
    const uint32_t voff = aoff;
    const uint32_t v1off = (uint32_t)((lane & 15) * ARB + 64);

    uint32_t qf[2][2][4];
    #pragma unroll
    for (int i = 0; i < 2; i++)
        #pragma unroll
        for (int ks = 0; ks < 2; ks++)
            ldsm_x4(qf[i][ks], QsB + aoff + (wm + 16 * i) * ARB + ks * 32);

    float O[2][5][4];
    #pragma unroll
    for (int i = 0; i < 2; i++)
        #pragma unroll
        for (int j = 0; j < 5; j++)
            #pragma unroll
            for (int t = 0; t < 4; t++) O[i][j][t] = 0.0f;

    #pragma unroll 1
    for (int nb = 0; nb < 8; nb++) {
        const int n0 = nb * 32;
        const int buf = nb & 1;

        // prefetch next cmb slice into the other warp-private buffer
        if (nb < 7) stage_cmb(buf ^ 1, n0 + 32);

        // ---- K fragments
        uint32_t kf[2][4][2];
        #pragma unroll
        for (int ks = 0; ks < 2; ks++)
            #pragma unroll
            for (int jp = 0; jp < 2; jp++) {
                uint32_t t4[4];
                ldsm_x4(t4, KsB + koff + (n0 + 16 * jp) * ARB + ks * 32);
                kf[ks][2 * jp][0] = t4[0]; kf[ks][2 * jp][1] = t4[1];
                kf[ks][2 * jp + 1][0] = t4[2]; kf[ks][2 * jp + 1][1] = t4[3];
            }

        // ---- S = Q K^T
        float S[2][4][4];
        #pragma unroll
        for (int i = 0; i < 2; i++)
            #pragma unroll
            for (int j = 0; j < 4; j++)
                #pragma unroll
                for (int t = 0; t < 4; t++) S[i][j][t] = 0.0f;
        #pragma unroll
        for (int ks = 0; ks < 2; ks++)
            #pragma unroll
            for (int j = 0; j < 4; j++) {
                mma_f16(S[0][j], qf[0][ks], kf[ks][j]);
                mma_f16(S[1][j], qf[1][ks], kf[ks][j]);
            }

        // ---- fold in cmb from warp-private smem (CF LDS) + shift
        {
            const char* cmB = smc + CMB_OFF + (warp * 2 + buf) * CWST;
            #pragma unroll
            for (int i = 0; i < 2; i++) {
                const char* p0 = cmB + (16 * i + qg) * CRB2 + tg * 4;
                const char* p1 = p0 + 8 * CRB2;
                #pragma unroll
                for (int j = 0; j < 4; j++) {
                    float2 v0 = __half22float2(*(const __half2*)(p0 + 16 * j));
                    float2 v1 = __half22float2(*(const __half2*)(p1 + 16 * j));
                    S[i][j][0] += v0.x + SHIFT;
                    S[i][j][1] += v0.y + SHIFT;
                    S[i][j][2] += v1.x + SHIFT;
                    S[i][j][3] += v1.y + SHIFT;
                }
            }
        }

        // ---- softmax: p = 2^S via f16x2 MUFU, straight into A-fragments
        uint32_t ph[2][2][4];
        #pragma unroll
        for (int i = 0; i < 2; i++)
            #pragma unroll
            for (int ks2 = 0; ks2 < 2; ks2++) {
                ph[i][ks2][0] = ex2h2(packh2(S[i][2 * ks2][0],     S[i][2 * ks2][1]));
                ph[i][ks2][1] = ex2h2(packh2(S[i][2 * ks2][2],     S[i][2 * ks2][3]));
                ph[i][ks2][2] = ex2h2(packh2(S[i][2 * ks2 + 1][0], S[i][2 * ks2 + 1][1]));
                ph[i][ks2][3] = ex2h2(packh2(S[i][2 * ks2 + 1][2], S[i][2 * ks2 + 1][3]));
            }

        // ---- V fragments + ones-column tile
        uint32_t vf[2][4][2], vf1[2][2];
        #pragma unroll
        for (int ks2 = 0; ks2 < 2; ks2++) {
            #pragma unroll
            for (int jp = 0; jp < 2; jp++) {
                uint32_t t4[4];
                ldsm_x4t(t4, VsB + voff + (n0 + 16 * ks2) * ARB + jp * 32);
                vf[ks2][2 * jp][0] = t4[0]; vf[ks2][2 * jp][1] = t4[1];
                vf[ks2][2 * jp + 1][0] = t4[2]; vf[ks2][2 * jp + 1][1] = t4[3];
            }
            ldsm_x2t(vf1[ks2], VsB + v1off + (n0 + 16 * ks2) * ARB);
        }

        // ---- O += P V (plus row-sum column)
        #pragma unroll
        for (int ks2 = 0; ks2 < 2; ks2++) {
            #pragma unroll
            for (int j = 0; j < 4; j++) {
                mma_f16(O[0][j], ph[0][ks2], vf[ks2][j]);
                mma_f16(O[1][j], ph[1][ks2], vf[ks2][j]);
            }
            mma_f16(O[0][4], ph[0][ks2], vf1[ks2]);
            mma_f16(O[1][4], ph[1][ks2], vf1[ks2]);
        }

        // wait for this iteration's prefetch (consumed next iter); warp-local only
        if (nb < 7) {
            asm volatile("cp.async.wait_group 0;");
            __syncwarp();
        }
    }

    #pragma unroll
    for (int i = 0; i < 2; i++) {
        float s0 = __shfl_sync(0xffffffffu, O[i][4][0], lane & 28);
        float s1 = __shfl_sync(0xffffffffu, O[i][4][2], lane & 28);
        float inv0 = 1.0f / s0, inv1 = 1.0f / s1;
        int row = wm + 16 * i + qg;
        #pragma unroll
        for (int j = 0; j < 4; j++) {
            int col = h * 32 + 8 * j + 2 * tg;
            *(__half2*)&g_att[((size_t)b * NTOK + row) * CDIM + col] =
                __floats2half2_rn(O[i][j][0] * inv0, O[i][j][1] * inv0);
            *(__half2*)&g_att[((size_t)b * NTOK + row + 8) * CDIM + col] =
                __floats2half2_rn(O[i][j][2] * inv1, O[i][j][3] * inv1);
        }
    }
}

// --------------------------------------------------------------------------
extern "C" void kernel_launch(void* const* d_in, const int* in_sizes, int n_in,
                              void* d_out, int out_size)
{
    const float* x      = (const float*)d_in[0];
    const float* mask   = (const float*)d_in[1];
    const float* qkv_w  = (const float*)d_in[2];
    const float* qkv_b  = (const float*)d_in[3];
    const float* proj_w = (const float*)d_in[4];
    const float* proj_b = (const float*)d_in[5];
    const float* table  = (const float*)d_in[6];
    const int*   ridx   = (const int*)d_in[7];
    float* out = (float*)d_out;

    __half *qkv_ptr, *att_ptr, *xh_ptr, *wh_ptr;
    cudaGetSymbolAddress((void**)&qkv_ptr, g_qkv);
    cudaGetSymbolAddress((void**)&att_ptr, g_att);
    cudaGetSymbolAddress((void**)&xh_ptr,  g_xh);
    cudaGetSymbolAddress((void**)&wh_ptr,  g_wh);
    __half* qkvw_h  = wh_ptr;
    __half* projw_h = wh_ptr + QKVD * CDIM;

    const int gemm_smem = 6 * GSTB;                       // 110592 B
    const int attn_smem = CMB_OFF + 8 * 2 * CWST;         // 61440 + 40960 = 102400 B
    cudaFuncSetAttribute((const void*)gemm_f16<true>,
                         cudaFuncAttributeMaxDynamicSharedMemorySize, gemm_smem);
    cudaFuncSetAttribute((const void*)gemm_f16<false>,
                         cudaFuncAttributeMaxDynamicSharedMemorySize, gemm_smem);
    cudaFuncSetAttribute((const void*)attn_f16,
                         cudaFuncAttributeMaxDynamicSharedMemorySize, attn_smem);

    // 0) prep: one fused conversion + bias gather + cmb combine
    tohalf3_kernel<<<(NX2 + NW2 + NP2 + 255) / 256, 256>>>(
        (const float2*)x, (const float2*)qkv_w, (const float2*)proj_w);
    bias16_kernel<<<NTOK * NTOK / 256, 256>>>(table, ridx);
    cmb_kernel<<<dim3(128, 64), 256>>>(mask);

    // 2) QKV projection -> fp16 (Q pre-scaled by scale*log2e)
    gemm_f16<true><<<dim3(QKVD / 128, (NBATCH * NTOK) / 128), 256, gemm_smem>>>(
        xh_ptr, qkvw_h, qkv_b, qkv_ptr, NBATCH * NTOK, QKVD, CDIM);

    // 3) window attention
    attn_f16<<<NBATCH * NH, 256, attn_smem>>>();

    // 4) output projection -> fp32 d_out
    gemm_f16<false><<<dim3(CDIM / 128, (NBATCH * NTOK) / 128), 256, gemm_smem>>>(
        att_ptr, projw_h, proj_b, out, NBATCH * NTOK, CDIM, CDIM);
}